// round 7
// baseline (speedup 1.0000x reference)
#include <cuda_runtime.h>
#include <cstdint>

#define B_  64
#define S_  512
#define H_  1024
#define L_  64
#define M_  (B_ * S_)      // 32768 rows
#define NB  4              // batches per CRF CTA

typedef unsigned long long u64;

// ---------------- scratch (no allocations allowed) ----------------
__device__ float g_llh[B_];
__device__ int   g_done;     // zero-init; reset by last finisher each launch

// ---------------- f32x2 helpers (sm_100+) ----------------
__device__ __forceinline__ u64 pack2(float lo, float hi) {
    u64 r;
    asm("mov.b64 %0, {%1, %2};" : "=l"(r) : "f"(lo), "f"(hi));
    return r;
}
__device__ __forceinline__ void fma2(u64 &d, u64 a, u64 b) {
    asm("fma.rn.f32x2 %0, %1, %2, %0;" : "+l"(d) : "l"(a), "l"(b));
}
__device__ __forceinline__ float2 unpk2(u64 v) {
    float2 r;
    asm("mov.b64 {%0, %1}, %2;" : "=f"(r.x), "=f"(r.y) : "l"(v));
    return r;
}

// ================= Emissions GEMM (f32x2) — unchanged (measured ~43us) =================
#define BM 128
#define BN 64
#define BK 16
#define AS_ROW (BM / 4 + 1)

__global__ __launch_bounds__(256) void gemm_kernel(
    const float* __restrict__ hs,
    const float* __restrict__ W,
    const float* __restrict__ bias,
    float* __restrict__ out)
{
    __shared__ float4 As4[BK][AS_ROW];
    __shared__ u64    Bs2[BK][32];

    const int tid = threadIdx.x;
    const int m0  = blockIdx.x * BM;
    const int tx  = tid & 15;
    const int ty  = tid >> 4;

    const int a_row = tid >> 2;
    const int a_k   = (tid & 3) * 4;
    const float* hsA0 = hs + (size_t)(m0 + a_row)      * H_ + a_k;
    const float* hsA1 = hs + (size_t)(m0 + a_row + 64) * H_ + a_k;
    const int b_k  = tid >> 4;
    const int b_c4 = tid & 15;
    const float* Wp = W + (size_t)b_k * L_ + b_c4 * 4;

    u64 acc[8][2];
    #pragma unroll
    for (int p = 0; p < 8; ++p) { acc[p][0] = 0ull; acc[p][1] = 0ull; }

    float4 a0 = *(const float4*)hsA0;
    float4 a1 = *(const float4*)hsA1;
    float4 bw = *(const float4*)Wp;

    float* As_f = (float*)As4;

    const int NCH = H_ / BK;
    for (int kc = 0; kc < NCH; ++kc) {
        As_f[(a_k + 0) * (AS_ROW * 4) + a_row] = a0.x;
        As_f[(a_k + 1) * (AS_ROW * 4) + a_row] = a0.y;
        As_f[(a_k + 2) * (AS_ROW * 4) + a_row] = a0.z;
        As_f[(a_k + 3) * (AS_ROW * 4) + a_row] = a0.w;
        As_f[(a_k + 0) * (AS_ROW * 4) + a_row + 64] = a1.x;
        As_f[(a_k + 1) * (AS_ROW * 4) + a_row + 64] = a1.y;
        As_f[(a_k + 2) * (AS_ROW * 4) + a_row + 64] = a1.z;
        As_f[(a_k + 3) * (AS_ROW * 4) + a_row + 64] = a1.w;
        Bs2[b_k][b_c4]      = pack2(bw.x, bw.y);
        Bs2[b_k][16 + b_c4] = pack2(bw.z, bw.w);
        __syncthreads();

        if (kc + 1 < NCH) {
            a0 = *(const float4*)(hsA0 + (kc + 1) * BK);
            a1 = *(const float4*)(hsA1 + (kc + 1) * BK);
            bw = *(const float4*)(Wp + (size_t)(kc + 1) * BK * L_);
        }

        #pragma unroll
        for (int kk = 0; kk < BK; ++kk) {
            const float4 av0 = As4[kk][ty * 2];
            const float4 av1 = As4[kk][ty * 2 + 1];
            const u64 b0 = Bs2[kk][tx];
            const u64 b1 = Bs2[kk][16 + tx];
            u64 ad[8];
            ad[0] = pack2(av0.x, av0.x); ad[1] = pack2(av0.y, av0.y);
            ad[2] = pack2(av0.z, av0.z); ad[3] = pack2(av0.w, av0.w);
            ad[4] = pack2(av1.x, av1.x); ad[5] = pack2(av1.y, av1.y);
            ad[6] = pack2(av1.z, av1.z); ad[7] = pack2(av1.w, av1.w);
            #pragma unroll
            for (int p = 0; p < 8; ++p) {
                fma2(acc[p][0], ad[p], b0);
                fma2(acc[p][1], ad[p], b1);
            }
        }
        __syncthreads();
    }

    float bb[4];
    #pragma unroll
    for (int q = 0; q < 4; ++q) bb[q] = bias[tx * 4 + q];

    #pragma unroll
    for (int p = 0; p < 8; ++p) {
        const size_t r = (size_t)(m0 + ty * 8 + p) * L_ + tx * 4;
        const float2 v0 = unpk2(acc[p][0]);
        const float2 v1 = unpk2(acc[p][1]);
        out[r + 0] = v0.x + bb[0];
        out[r + 1] = v0.y + bb[1];
        out[r + 2] = v1.x + bb[2];
        out[r + 3] = v1.y + bb[3];
    }
}

// ================= CRF kernel: 4 batches per CTA (lockstep), scalar inner =================
// 256 threads = 4 batch-groups x 64 threads. Thread (bg, j): batch blockIdx*4+bg, label j.
// Exp-domain scan, E[i]=exp(trans[i][j]) in regs, exp(em) computed at prefetch (depth 2),
// renorm every 8 steps. All batches step in lockstep to the CTA max length; per-batch
// state updates predicated on t < len. 2 warps/SMSP from independent batches hide latency.
__global__ __launch_bounds__(256) void crf_kernel(
    const float* __restrict__ em,          // [B,S,L] (4B-aligned only)
    const int*   __restrict__ mask,        // [B,S]
    const int*   __restrict__ labels,      // [B,S] int32
    const float* __restrict__ start_t,     // [L]
    const float* __restrict__ end_t,       // [L]
    const float* __restrict__ trans,       // [L,L]
    float* __restrict__ loss_out)
{
    const unsigned FULL = 0xffffffffu;
    const int tid = threadIdx.x;
    const int bg  = tid >> 6;        // 0..3
    const int j   = tid & 63;        // label
    const int b   = blockIdx.x * NB + bg;

    __shared__ float4 qb4[NB][2][L_ / 4];
    __shared__ float  red[NB][2];
    __shared__ int    lens[NB];

    // ---- sequence length (mask is a prefix): 64 threads, 8 elems each ----
    {
        const int* mrow = mask + (size_t)b * S_;
        int cnt = 0;
        #pragma unroll
        for (int t = j; t < S_; t += 64) cnt += mrow[t];
        #pragma unroll
        for (int s = 16; s > 0; s >>= 1) cnt += __shfl_xor_sync(FULL, cnt, s);
        if ((j & 31) == 0) red[bg][j >> 5] = (float)cnt;
    }
    __syncthreads();
    const int len = (int)(red[bg][0] + red[bg][1]);
    if (j == 0) lens[bg] = len;
    __syncthreads();
    const int maxlen = max(max(lens[0], lens[1]), max(lens[2], lens[3]));
    __syncthreads();

    // ---- per-thread constants ----
    float E[L_];
    #pragma unroll
    for (int i = 0; i < L_; ++i)
        E[i] = __expf(trans[i * L_ + j]);
    const float eEnd = __expf(end_t[j]);

    const float* emb = em + (size_t)b * S_ * L_;

    // ---- init: alpha0 = start + em[0], renorm by batch max ----
    const float alpha0 = start_t[j] + emb[j];
    ((float*)qb4[bg][1])[j] = alpha0;
    __syncthreads();
    float m0v = -3.4e38f;
    #pragma unroll
    for (int i4 = 0; i4 < 16; ++i4) {
        const float4 v = qb4[bg][1][i4];
        m0v = fmaxf(m0v, fmaxf(fmaxf(v.x, v.y), fmaxf(v.z, v.w)));
    }
    float c = m0v;
    ((float*)qb4[bg][0])[j] = __expf(alpha0 - m0v);
    __syncthreads();

    // ---- exp(em) prefetch depth 2 ----
    float exA = (1 < len) ? __expf(emb[(size_t)1 * L_ + j]) : 1.0f;
    float exB = (2 < len) ? __expf(emb[(size_t)2 * L_ + j]) : 1.0f;

    // ---- main scan (lockstep over CTA) ----
    float pending = 1.0f;
    int prev = 0;
    for (int t = 1; t < maxlen; ++t) {
        const bool act = (t < len);
        const float ex = exA;
        exA = exB;
        exB = (t + 2 < len) ? __expf(emb[(size_t)(t + 2) * L_ + j]) : 1.0f;

        float v0 = 0.f, v1 = 0.f, v2 = 0.f, v3 = 0.f;
        const float4* qp = qb4[bg][prev];
        #pragma unroll
        for (int i4 = 0; i4 < 16; ++i4) {
            const float4 q4 = qp[i4];
            v0 = fmaf(q4.x, E[i4 * 4 + 0], v0);
            v1 = fmaf(q4.y, E[i4 * 4 + 1], v1);
            v2 = fmaf(q4.z, E[i4 * 4 + 2], v2);
            v3 = fmaf(q4.w, E[i4 * 4 + 3], v3);
        }
        const float v = (v0 + v1) + (v2 + v3);
        const float q = v * ex * pending;
        const int cur = prev ^ 1;
        if (act) ((float*)qb4[bg][cur])[j] = q;
        __syncthreads();

        if ((t & 7) == 0) {
            if (act) {
                float mx = 0.0f;
                #pragma unroll
                for (int i4 = 0; i4 < 16; ++i4) {
                    const float4 u = qb4[bg][cur][i4];
                    mx = fmaxf(mx, fmaxf(fmaxf(u.x, u.y), fmaxf(u.z, u.w)));
                }
                pending = 1.0f / mx;
                c += __logf(mx);
            }
        } else if (act) {
            pending = 1.0f;
        }
        if (act) prev = cur;
    }

    // ---- log_z = c + log(pending) + log(sum_j q[j]*exp(end[j])) ----
    {
        float sv = ((float*)qb4[bg][prev])[j] * eEnd;
        #pragma unroll
        for (int s = 16; s > 0; s >>= 1) sv += __shfl_xor_sync(FULL, sv, s);
        if ((j & 31) == 0) red[bg][j >> 5] = sv;
    }
    __syncthreads();
    const float logz = c + __logf(pending) + __logf(red[bg][0] + red[bg][1]);
    __syncthreads();

    // ---- numerator (strided over t); indices clamped ----
    const int* lab = labels + (size_t)b * S_;
    float part = 0.0f;
    for (int t = 1 + j; t < len; t += 64) {
        const int lp = lab[t - 1];
        const int lc = lab[t];
        const int tp = ((lp == -100) ? 0 : lp) & 63;
        const int tc = ((lc == -100) ? 0 : lc) & 63;
        part += trans[tp * L_ + tc] + emb[(size_t)t * L_ + tc];
    }
    if (j == 0) {
        const int l0 = lab[0];
        const int t0 = ((l0 == -100) ? 0 : l0) & 63;
        const int ll = lab[len - 1];
        const int tl = ((ll == -100) ? 0 : ll) & 63;
        part += start_t[t0] + emb[t0] + end_t[tl];
    }
    #pragma unroll
    for (int s = 16; s > 0; s >>= 1) part += __shfl_xor_sync(FULL, part, s);
    if ((j & 31) == 0) red[bg][j >> 5] = part;
    __syncthreads();

    // ---- fused loss: last batch to finish reduces all llh ----
    if (j == 0) {
        g_llh[b] = (red[bg][0] + red[bg][1]) - logz;
        __threadfence();
        const int old = atomicAdd(&g_done, 1);
        if (old == B_ - 1) {
            float sum = 0.0f;
            #pragma unroll 8
            for (int i = 0; i < B_; ++i) sum += __ldcg(&g_llh[i]);
            loss_out[0] = -sum / (float)B_;
            g_done = 0;   // reset for next graph replay
        }
    }
}

// ================= launch =================
extern "C" void kernel_launch(void* const* d_in, const int* in_sizes, int n_in,
                              void* d_out, int out_size)
{
    const float* hs     = (const float*)d_in[0];
    const int*   mask   = (const int*)d_in[1];
    const int*   labels = (const int*)d_in[2];
    const float* W      = (const float*)d_in[3];
    const float* bias   = (const float*)d_in[4];
    const float* st     = (const float*)d_in[5];
    const float* en     = (const float*)d_in[6];
    const float* tr     = (const float*)d_in[7];

    float* out = (float*)d_out;
    const int off = (out_size > M_ * L_) ? (out_size - M_ * L_) : 0;
    float* emis = out + off;

    gemm_kernel<<<M_ / BM, 256>>>(hs, W, bias, emis);
    crf_kernel<<<B_ / NB, NB * 64>>>(emis, mask, labels, st, en, tr, out);
}

// round 10
// speedup vs baseline: 1.3623x; 1.3623x over previous
#include <cuda_runtime.h>
#include <cstdint>

#define B_  64
#define S_  512
#define H_  1024
#define L_  64
#define M_  (B_ * S_)      // 32768 rows

typedef unsigned long long u64;

// ---------------- scratch (no allocations allowed) ----------------
__device__ float g_llh[B_];
__device__ int   g_done;     // zero-init; reset by last finisher each launch

// ---------------- f32x2 helpers (sm_100+) ----------------
__device__ __forceinline__ u64 pack2(float lo, float hi) {
    u64 r;
    asm("mov.b64 %0, {%1, %2};" : "=l"(r) : "f"(lo), "f"(hi));
    return r;
}
__device__ __forceinline__ void fma2(u64 &d, u64 a, u64 b) {
    asm("fma.rn.f32x2 %0, %1, %2, %0;" : "+l"(d) : "l"(a), "l"(b));
}
__device__ __forceinline__ float2 unpk2(u64 v) {
    float2 r;
    asm("mov.b64 {%0, %1}, %2;" : "=f"(r.x), "=f"(r.y) : "l"(v));
    return r;
}

// ================= Emissions GEMM (f32x2) — R5 version, measured ~43us =================
#define BM 128
#define BN 64
#define BK 16
#define AS_ROW (BM / 4 + 1)

__global__ __launch_bounds__(256) void gemm_kernel(
    const float* __restrict__ hs,
    const float* __restrict__ W,
    const float* __restrict__ bias,
    float* __restrict__ out)
{
    __shared__ float4 As4[BK][AS_ROW];
    __shared__ u64    Bs2[BK][32];

    const int tid = threadIdx.x;
    const int m0  = blockIdx.x * BM;
    const int tx  = tid & 15;
    const int ty  = tid >> 4;

    const int a_row = tid >> 2;
    const int a_k   = (tid & 3) * 4;
    const float* hsA0 = hs + (size_t)(m0 + a_row)      * H_ + a_k;
    const float* hsA1 = hs + (size_t)(m0 + a_row + 64) * H_ + a_k;
    const int b_k  = tid >> 4;
    const int b_c4 = tid & 15;
    const float* Wp = W + (size_t)b_k * L_ + b_c4 * 4;

    u64 acc[8][2];
    #pragma unroll
    for (int p = 0; p < 8; ++p) { acc[p][0] = 0ull; acc[p][1] = 0ull; }

    float4 a0 = *(const float4*)hsA0;
    float4 a1 = *(const float4*)hsA1;
    float4 bw = *(const float4*)Wp;

    float* As_f = (float*)As4;

    const int NCH = H_ / BK;
    for (int kc = 0; kc < NCH; ++kc) {
        As_f[(a_k + 0) * (AS_ROW * 4) + a_row] = a0.x;
        As_f[(a_k + 1) * (AS_ROW * 4) + a_row] = a0.y;
        As_f[(a_k + 2) * (AS_ROW * 4) + a_row] = a0.z;
        As_f[(a_k + 3) * (AS_ROW * 4) + a_row] = a0.w;
        As_f[(a_k + 0) * (AS_ROW * 4) + a_row + 64] = a1.x;
        As_f[(a_k + 1) * (AS_ROW * 4) + a_row + 64] = a1.y;
        As_f[(a_k + 2) * (AS_ROW * 4) + a_row + 64] = a1.z;
        As_f[(a_k + 3) * (AS_ROW * 4) + a_row + 64] = a1.w;
        Bs2[b_k][b_c4]      = pack2(bw.x, bw.y);
        Bs2[b_k][16 + b_c4] = pack2(bw.z, bw.w);
        __syncthreads();

        if (kc + 1 < NCH) {
            a0 = *(const float4*)(hsA0 + (kc + 1) * BK);
            a1 = *(const float4*)(hsA1 + (kc + 1) * BK);
            bw = *(const float4*)(Wp + (size_t)(kc + 1) * BK * L_);
        }

        #pragma unroll
        for (int kk = 0; kk < BK; ++kk) {
            const float4 av0 = As4[kk][ty * 2];
            const float4 av1 = As4[kk][ty * 2 + 1];
            const u64 b0 = Bs2[kk][tx];
            const u64 b1 = Bs2[kk][16 + tx];
            u64 ad[8];
            ad[0] = pack2(av0.x, av0.x); ad[1] = pack2(av0.y, av0.y);
            ad[2] = pack2(av0.z, av0.z); ad[3] = pack2(av0.w, av0.w);
            ad[4] = pack2(av1.x, av1.x); ad[5] = pack2(av1.y, av1.y);
            ad[6] = pack2(av1.z, av1.z); ad[7] = pack2(av1.w, av1.w);
            #pragma unroll
            for (int p = 0; p < 8; ++p) {
                fma2(acc[p][0], ad[p], b0);
                fma2(acc[p][1], ad[p], b1);
            }
        }
        __syncthreads();
    }

    float bb[4];
    #pragma unroll
    for (int q = 0; q < 4; ++q) bb[q] = bias[tx * 4 + q];

    #pragma unroll
    for (int p = 0; p < 8; ++p) {
        const size_t r = (size_t)(m0 + ty * 8 + p) * L_ + tx * 4;
        const float2 v0 = unpk2(acc[p][0]);
        const float2 v1 = unpk2(acc[p][1]);
        out[r + 0] = v0.x + bb[0];
        out[r + 1] = v0.y + bb[1];
        out[r + 2] = v1.x + bb[2];
        out[r + 3] = v1.y + bb[3];
    }
}

// ================= CRF kernel — R4 structure (measured best ~570 cyc/step) =================
// One CTA per batch, 64 threads (thread j owns label j). Scalar fma inner loop,
// float4 LDS of q. Deltas vs R4: exp(em) computed at prefetch (depth 2), fused loss.
__global__ __launch_bounds__(64) void crf_kernel(
    const float* __restrict__ em,          // [B,S,L] (4B-aligned only)
    const int*   __restrict__ mask,        // [B,S]
    const int*   __restrict__ labels,      // [B,S] int32
    const float* __restrict__ start_t,     // [L]
    const float* __restrict__ end_t,       // [L]
    const float* __restrict__ trans,       // [L,L]
    float* __restrict__ loss_out)
{
    const int b = blockIdx.x;
    const int j = threadIdx.x;

    __shared__ float4 qbuf4[2][L_ / 4];
    __shared__ float  red[L_];

    // ---- sequence length (mask is a prefix) ----
    {
        int cnt = 0;
        const int* mrow = mask + (size_t)b * S_;
        #pragma unroll
        for (int t = j; t < S_; t += L_) cnt += mrow[t];
        red[j] = (float)cnt;
    }
    __syncthreads();
    #pragma unroll
    for (int s = 32; s > 0; s >>= 1) {
        if (j < s) red[j] += red[j + s];
        __syncthreads();
    }
    const int len = (int)red[0];
    __syncthreads();

    // ---- per-thread constants ----
    float E[L_];
    #pragma unroll
    for (int i = 0; i < L_; ++i)
        E[i] = __expf(trans[i * L_ + j]);
    const float eEnd = __expf(end_t[j]);

    const float* emb = em + (size_t)b * S_ * L_;

    // ---- init: alpha0 = start + em[0], renorm by block max ----
    const float alpha0 = start_t[j] + emb[j];
    ((float*)qbuf4[1])[j] = alpha0;
    __syncthreads();
    float m0v = -3.4e38f;
    #pragma unroll
    for (int i4 = 0; i4 < 16; ++i4) {
        const float4 v = qbuf4[1][i4];
        m0v = fmaxf(m0v, fmaxf(fmaxf(v.x, v.y), fmaxf(v.z, v.w)));
    }
    float c = m0v;
    ((float*)qbuf4[0])[j] = __expf(alpha0 - m0v);
    __syncthreads();

    // ---- exp(em) prefetch depth 2 (MUFU + LDG off the critical path) ----
    float exA = (1 < len) ? __expf(emb[(size_t)1 * L_ + j]) : 1.0f;
    float exB = (2 < len) ? __expf(emb[(size_t)2 * L_ + j]) : 1.0f;

    // ---- main scan ----
    float pending = 1.0f;
    int prev = 0;
    for (int t = 1; t < len; ++t) {
        const float ex = exA;
        exA = exB;
        exB = (t + 2 < len) ? __expf(emb[(size_t)(t + 2) * L_ + j]) : 1.0f;

        float v0 = 0.f, v1 = 0.f, v2 = 0.f, v3 = 0.f;
        const float4* qp = qbuf4[prev];
        #pragma unroll
        for (int i4 = 0; i4 < 16; ++i4) {
            const float4 q4 = qp[i4];
            v0 = fmaf(q4.x, E[i4 * 4 + 0], v0);
            v1 = fmaf(q4.y, E[i4 * 4 + 1], v1);
            v2 = fmaf(q4.z, E[i4 * 4 + 2], v2);
            v3 = fmaf(q4.w, E[i4 * 4 + 3], v3);
        }
        const float v = (v0 + v1) + (v2 + v3);
        const float q = v * ex * pending;
        const int cur = prev ^ 1;
        ((float*)qbuf4[cur])[j] = q;
        __syncthreads();

        if ((t & 7) == 0) {
            float mx = 0.0f;
            #pragma unroll
            for (int i4 = 0; i4 < 16; ++i4) {
                const float4 u = qbuf4[cur][i4];
                mx = fmaxf(mx, fmaxf(fmaxf(u.x, u.y), fmaxf(u.z, u.w)));
            }
            pending = 1.0f / mx;
            c += __logf(mx);
        } else {
            pending = 1.0f;
        }
        prev = cur;
    }

    // ---- log_z = c + log(pending) + log(sum_j q[j]*exp(end[j])) ----
    red[j] = ((float*)qbuf4[prev])[j] * eEnd;
    __syncthreads();
    #pragma unroll
    for (int s = 32; s > 0; s >>= 1) {
        if (j < s) red[j] += red[j + s];
        __syncthreads();
    }
    const float logz = c + __logf(pending) + __logf(red[0]);
    __syncthreads();

    // ---- numerator (parallel over t, strided); indices clamped ----
    const int* lab = labels + (size_t)b * S_;
    float part = 0.0f;
    for (int t = 1 + j; t < len; t += L_) {
        const int lp = lab[t - 1];
        const int lc = lab[t];
        const int tp = ((lp == -100) ? 0 : lp) & 63;
        const int tc = ((lc == -100) ? 0 : lc) & 63;
        part += trans[tp * L_ + tc] + emb[(size_t)t * L_ + tc];
    }
    if (j == 0) {
        const int l0 = lab[0];
        const int t0 = ((l0 == -100) ? 0 : l0) & 63;
        const int ll = lab[len - 1];
        const int tl = ((ll == -100) ? 0 : ll) & 63;
        part += start_t[t0] + emb[t0] + end_t[tl];
    }
    red[j] = part;
    __syncthreads();
    #pragma unroll
    for (int s = 32; s > 0; s >>= 1) {
        if (j < s) red[j] += red[j + s];
        __syncthreads();
    }

    // ---- fused loss: last CTA reduces all llh ----
    if (j == 0) {
        g_llh[b] = red[0] - logz;
        __threadfence();
        const int old = atomicAdd(&g_done, 1);
        if (old == B_ - 1) {
            float sum = 0.0f;
            #pragma unroll 8
            for (int i = 0; i < B_; ++i) sum += __ldcg(&g_llh[i]);
            loss_out[0] = -sum / (float)B_;
            g_done = 0;   // reset for next graph replay
        }
    }
}

// ================= launch =================
extern "C" void kernel_launch(void* const* d_in, const int* in_sizes, int n_in,
                              void* d_out, int out_size)
{
    const float* hs     = (const float*)d_in[0];
    const int*   mask   = (const int*)d_in[1];
    const int*   labels = (const int*)d_in[2];
    const float* W      = (const float*)d_in[3];
    const float* bias   = (const float*)d_in[4];
    const float* st     = (const float*)d_in[5];
    const float* en     = (const float*)d_in[6];
    const float* tr     = (const float*)d_in[7];

    float* out = (float*)d_out;
    const int off = (out_size > M_ * L_) ? (out_size - M_ * L_) : 0;
    float* emis = out + off;

    gemm_kernel<<<M_ / BM, 256>>>(hs, W, bias, emis);
    crf_kernel<<<B_, L_>>>(emis, mask, labels, st, en, tr, out);
}